// round 15
// baseline (speedup 1.0000x reference)
#include <cuda_runtime.h>
#include <cuda_bf16.h>
#include <cstdint>

#define BBATCH 8
#define DDIM 1024
#define LDIM 2048
#define CAUCHY_E 1.0100501670841680f
#define PI_F 3.14159265358979323846f

constexpr long long C_BDL = (long long)BBATCH * DDIM * LDIM;
constexpr long long C_BDD = (long long)BBATCH * DDIM * DDIM;
constexpr long long C_BLL = (long long)BBATCH * LDIM * LDIM;
constexpr long long C_W   = 4LL * 3 * DDIM * DDIM;
constexpr long long EDL   = (long long)DDIM * LDIM;
constexpr long long DxDc  = (long long)DDIM * DDIM;

constexpr long long oGd   = 0;
constexpr long long oGlT  = oGd   + C_BDD * 4;
constexpr long long oXT   = oGlT  + C_BLL * 4;
constexpr long long oT0   = oXT   + C_BDL * 2;   // WTall, PTall, Wc[4]
constexpr long long oT1   = oT0   + C_BDL * 2;   // ubuf, bc
constexpr long long oDSXT = oT1   + C_BDL * 2;
constexpr long long oDCXT = oDSXT + C_BDL * 2;
constexpr long long oLSXT = oDCXT + C_BDL * 2;
constexpr long long oLCXT = oLSXT + C_BDL * 2;
constexpr long long oDSX  = oLCXT + C_BDL * 2;
constexpr long long oDCX  = oDSX  + C_BDL * 2;
constexpr long long oWB   = oDCX  + C_BDL * 2;
constexpr long long oGDB  = oWB   + C_W   * 2;
constexpr long long oSLT  = oGDB  + C_BDD * 2;
constexpr long long oZB   = oSLT  + C_BLL * 2;
constexpr long long oNSD  = oZB   + C_BDL * 2;
constexpr long long oNCD  = oNSD  + BBATCH * DDIM * 4;
constexpr long long oNSL  = oNCD  + BBATCH * DDIM * 4;
constexpr long long oNCL  = oNSL  + BBATCH * LDIM * 4;
constexpr long long oCSD  = oNCL  + BBATCH * LDIM * 4;
constexpr long long oCSL  = oCSD  + BBATCH * DDIM * 4;
constexpr long long SCRB  = oCSL  + BBATCH * LDIM * 4;
__device__ __align__(1024) unsigned char g_scr[SCRB];

// ---------------------------------------------------------------------------
__device__ __forceinline__ void ldm4(uint32_t* r, const void* p) {
    uint32_t a = (uint32_t)__cvta_generic_to_shared(p);
    asm volatile("ldmatrix.sync.aligned.m8n8.x4.shared.b16 {%0,%1,%2,%3}, [%4];"
                 : "=r"(r[0]), "=r"(r[1]), "=r"(r[2]), "=r"(r[3]) : "r"(a));
}
__device__ __forceinline__ void mma_bf16(float* d, const uint32_t* a, const uint32_t* b) {
    asm volatile(
        "mma.sync.aligned.m16n8k16.row.col.f32.bf16.bf16.f32 "
        "{%0,%1,%2,%3}, {%4,%5,%6,%7}, {%8,%9}, {%0,%1,%2,%3};"
        : "+f"(d[0]), "+f"(d[1]), "+f"(d[2]), "+f"(d[3])
        : "r"(a[0]), "r"(a[1]), "r"(a[2]), "r"(a[3]), "r"(b[0]), "r"(b[1]));
}
__device__ __forceinline__ void cpa16(void* dst, const void* src) {
    uint32_t d = (uint32_t)__cvta_generic_to_shared(dst);
    asm volatile("cp.async.cg.shared.global [%0], [%1], 16;" :: "r"(d), "l"(src));
}
__device__ __forceinline__ void cpa_commit() { asm volatile("cp.async.commit_group;"); }
template<int N>
__device__ __forceinline__ void cpa_wait() { asm volatile("cp.async.wait_group %0;" :: "n"(N)); }

// ---------------------------------------------------------------------------
// HMMA bf16 GEMM: C[M,N] = A[M,K] * B[N,K]^T, both K-major bf16.
// EPI: 0 fp32 out; 1 +bias[col] bf16 out; 2 (acc+resid)/2 fp32 out; 3 bf16 out;
//      4 cauchy fused (bias=row-norms stride M/batch, resid=col-norms stride N/batch).
// Tile 128x256x64; 8 warps 2x4, warp tile 64x64. M%128==0, N%256==0, K%64==0.
// ---------------------------------------------------------------------------
template<int EPI>
__global__ void __launch_bounds__(256, 1)
hgemm(const __nv_bfloat16* __restrict__ Ag, const __nv_bfloat16* __restrict__ Bg,
      void* __restrict__ Cg, const float* __restrict__ bias,
      const float* __restrict__ resid,
      int M, int N, int K, long long sA, long long sB, long long sC)
{
    constexpr int BK = 64, LDS = 72;
    extern __shared__ __nv_bfloat16 smem[];
    __nv_bfloat16* Abase = smem;                    // [2][128][72]
    __nv_bfloat16* Bbase = smem + 2 * 128 * LDS;    // [2][256][72]

    const int tid = threadIdx.x, lane = tid & 31, wid = tid >> 5;
    const int wR = wid & 1, wC = wid >> 1;
    const int bz = blockIdx.z;
    const __nv_bfloat16* A = Ag + bz * sA;
    const __nv_bfloat16* B = Bg + bz * sB;
    const int mBase = blockIdx.y * 128, nBase = blockIdx.x * 256;
    const int mW = wR * 64, nW = wC * 64;

    auto fetch = [&](int t, int buf) {
        const int kb = t * BK;
#pragma unroll
        for (int i = 0; i < 4; ++i) {               // A: 128x64 = 1024 chunks
            const int fi = tid + i * 256;
            const int r = fi >> 3, c = (fi & 7) << 3;
            cpa16(Abase + (buf * 128 + r) * LDS + c,
                  A + (long long)(mBase + r) * K + kb + c);
        }
#pragma unroll
        for (int i = 0; i < 8; ++i) {               // B: 256x64 = 2048 chunks
            const int fi = tid + i * 256;
            const int r = fi >> 3, c = (fi & 7) << 3;
            cpa16(Bbase + (buf * 256 + r) * LDS + c,
                  B + (long long)(nBase + r) * K + kb + c);
        }
        cpa_commit();
    };

    float acc[4][8][4] = {};
    const int nT = K / BK;

    fetch(0, 0);
    for (int t = 0; t < nT; ++t) {
        const int buf = t & 1;
        if (t + 1 < nT) { fetch(t + 1, buf ^ 1); cpa_wait<1>(); }
        else            { cpa_wait<0>(); }
        __syncthreads();

        const __nv_bfloat16* As = Abase + buf * 128 * LDS;
        const __nv_bfloat16* Bs = Bbase + buf * 256 * LDS;
#pragma unroll
        for (int kk = 0; kk < BK; kk += 16) {
            uint32_t a[4][4], b[8][2];
#pragma unroll
            for (int mt = 0; mt < 4; ++mt)
                ldm4(a[mt], As + (mW + mt * 16 + (lane & 15)) * LDS + kk + ((lane >> 4) << 3));
#pragma unroll
            for (int p = 0; p < 4; ++p) {
                uint32_t r4[4];
                ldm4(r4, Bs + (nW + p * 16 + (lane & 15)) * LDS + kk + ((lane >> 4) << 3));
                b[2 * p + 0][0] = r4[0]; b[2 * p + 0][1] = r4[2];
                b[2 * p + 1][0] = r4[1]; b[2 * p + 1][1] = r4[3];
            }
#pragma unroll
            for (int mt = 0; mt < 4; ++mt)
#pragma unroll
                for (int nt = 0; nt < 8; ++nt)
                    mma_bf16(acc[mt][nt], a[mt], b[nt]);
        }
        __syncthreads();
    }

    const int g = lane >> 2, tq = lane & 3;
#pragma unroll
    for (int mt = 0; mt < 4; ++mt) {
#pragma unroll
        for (int half = 0; half < 2; ++half) {
            const int row = mBase + mW + mt * 16 + g + half * 8;
            const float nsr = (EPI == 4) ? __ldg(&bias[(long long)bz * M + row]) : 0.f;
#pragma unroll
            for (int nt = 0; nt < 8; ++nt) {
                const int col = nBase + nW + nt * 8 + tq * 2;
                const long long off = (long long)row * N + col;
                float v0 = acc[mt][nt][half * 2 + 0];
                float v1 = acc[mt][nt][half * 2 + 1];
                if (EPI == 1) {
                    v0 += __ldg(&bias[col]);
                    v1 += __ldg(&bias[col + 1]);
                }
                if (EPI == 0) {
                    float* C = (float*)Cg + bz * sC + off;
                    *reinterpret_cast<float2*>(C) = make_float2(v0, v1);
                } else if (EPI == 2) {
                    float* C = (float*)Cg + bz * sC + off;
                    const float* Rp = resid + bz * sC + off;
                    float2 r2 = *reinterpret_cast<const float2*>(Rp);
                    *reinterpret_cast<float2*>(C) = make_float2((v0 + r2.x) * 0.5f,
                                                                (v1 + r2.y) * 0.5f);
                } else if (EPI == 4) {
                    const float nc0 = __ldg(&resid[(long long)bz * N + col]);
                    const float nc1 = __ldg(&resid[(long long)bz * N + col + 1]);
                    float w0 = __powf((v0 * v0) / (nsr * nc0), CAUCHY_E);
                    float w1 = __powf((v1 * v1) / (nsr * nc1), CAUCHY_E);
                    if (row == col) w0 -= 1.f;
                    if (row == col + 1) w1 -= 1.f;
                    w0 = fmaxf(0.5f - 0.5f * __cosf(PI_F * w0), 0.f);
                    w1 = fmaxf(0.5f - 0.5f * __cosf(PI_F * w1), 0.f);
                    float* C = (float*)Cg + bz * sC + off;
                    *reinterpret_cast<float2*>(C) = make_float2(__expf(w0), __expf(w1));
                } else {
                    __nv_bfloat16* C = (__nv_bfloat16*)Cg + bz * sC + off;
                    *reinterpret_cast<__nv_bfloat162*>(C) = __floats2bfloat162_rn(v0, v1);
                }
            }
        }
    }
}

// ----------------------------- elementwise --------------------------------
__device__ __forceinline__ float block_reduce_sum(float v) {
    __shared__ float sh[32];
#pragma unroll
    for (int o = 16; o; o >>= 1) v += __shfl_xor_sync(0xFFFFFFFFu, v, o);
    const int lane = threadIdx.x & 31, w = threadIdx.x >> 5;
    if (lane == 0) sh[w] = v;
    __syncthreads();
    if (w == 0) {
        v = (lane < (int)(blockDim.x >> 5)) ? sh[lane] : 0.f;
#pragma unroll
        for (int o = 16; o; o >>= 1) v += __shfl_xor_sync(0xFFFFFFFFu, v, o);
        if (lane == 0) sh[0] = v;
    }
    __syncthreads();
    return sh[0];
}

__global__ void f2b_kernel(const float* __restrict__ in, __nv_bfloat16* __restrict__ out, long long n) {
    for (long long i = (long long)blockIdx.x * blockDim.x + threadIdx.x; i < n;
         i += (long long)gridDim.x * blockDim.x)
        out[i] = __float2bfloat16(in[i]);
}

__global__ void tr_f2b(const float* __restrict__ in, __nv_bfloat16* __restrict__ out, int R, int C) {
    __shared__ float sh[32][33];
    const long long bb = blockIdx.z;
    const float* I = in + bb * (long long)R * C;
    __nv_bfloat16* O = out + bb * (long long)R * C;
    const int c0 = blockIdx.x * 32, r0 = blockIdx.y * 32;
    const int tx = threadIdx.x, ty = threadIdx.y;
#pragma unroll
    for (int i = 0; i < 32; i += 8) sh[ty + i][tx] = I[(long long)(r0 + ty + i) * C + c0 + tx];
    __syncthreads();
#pragma unroll
    for (int i = 0; i < 32; i += 8)
        O[(long long)(c0 + ty + i) * R + r0 + tx] = __float2bfloat16(sh[tx][ty + i]);
}

__global__ void tr_b2b(const __nv_bfloat16* __restrict__ in, __nv_bfloat16* __restrict__ out,
                       int R, int C, long long inStride, long long outStride) {
    __shared__ __nv_bfloat16 sh[32][33];
    const long long bb = blockIdx.z;
    const __nv_bfloat16* I = in + bb * inStride;
    __nv_bfloat16* O = out + bb * outStride;
    const int c0 = blockIdx.x * 32, r0 = blockIdx.y * 32;
    const int tx = threadIdx.x, ty = threadIdx.y;
#pragma unroll
    for (int i = 0; i < 32; i += 8) sh[ty + i][tx] = I[(long long)(r0 + ty + i) * C + c0 + tx];
    __syncthreads();
#pragma unroll
    for (int i = 0; i < 32; i += 8) O[(long long)(c0 + ty + i) * R + r0 + tx] = sh[tx][ty + i];
}

__global__ void matvec_f(const float* __restrict__ W, const float* __restrict__ v,
                         const float* __restrict__ b, float* __restrict__ out, int n) {
    const int row = blockIdx.x;
    const float* w = W + (long long)row * n;
    float s = 0.f;
    for (int i = threadIdx.x; i < n; i += blockDim.x) s = fmaf(w[i], v[i], s);
    s = block_reduce_sum(s);
    if (threadIdx.x == 0) out[row] = s + b[row];
}

__global__ void rownorm_b(const __nv_bfloat16* __restrict__ X, float* __restrict__ out, int C) {
    const __nv_bfloat16* p = X + (long long)blockIdx.x * C;
    float s = 0.f;
    for (int i = threadIdx.x; i < C; i += blockDim.x) {
        float v = __bfloat162float(p[i]);
        s = fmaf(v, v, s);
    }
    s = block_reduce_sum(s);
    if (threadIdx.x == 0) out[blockIdx.x] = s;
}

__global__ void colsum(const float* __restrict__ G, float* __restrict__ out, int n) {
    const int b = blockIdx.y;
    const int q = blockIdx.x * blockDim.x + threadIdx.x;
    const float* p = G + (long long)b * n * n + q;
    float s = 0.f;
    for (int r = 0; r < n; ++r) s += p[(long long)r * n];
    out[b * n + q] = s;
}

__global__ void divcol_b(const float* __restrict__ G, const float* __restrict__ cs,
                         __nv_bfloat16* __restrict__ out, int n, int sq_shift) {
    const long long tot = (long long)BBATCH * n * n;
    for (long long idx = (long long)blockIdx.x * blockDim.x + threadIdx.x; idx < tot;
         idx += (long long)gridDim.x * blockDim.x) {
        const int q = (int)(idx & (n - 1));
        const int b = (int)(idx >> sq_shift);
        out[idx] = __float2bfloat16(G[idx] / cs[b * n + q]);
    }
}

// ---------------------------------------------------------------------------
extern "C" void kernel_launch(void* const* d_in, const int* in_sizes, int n_in,
                              void* d_out, int out_size) {
    const float* x = (const float*)d_in[0];
    const float* Wf[4] = {(const float*)d_in[1], (const float*)d_in[3],
                          (const float*)d_in[5], (const float*)d_in[7]};
    const float* bfv[4] = {(const float*)d_in[2], (const float*)d_in[4],
                           (const float*)d_in[6], (const float*)d_in[8]};
    float* y = (float*)d_out;

    unsigned char* scr = nullptr;
    cudaGetSymbolAddress((void**)&scr, g_scr);

    float* Gd  = (float*)(scr + oGd);
    float* GlT = (float*)(scr + oGlT);
    __nv_bfloat16* xT   = (__nv_bfloat16*)(scr + oXT);
    __nv_bfloat16* dsxT = (__nv_bfloat16*)(scr + oDSXT);
    __nv_bfloat16* dcxT = (__nv_bfloat16*)(scr + oDCXT);
    __nv_bfloat16* lsxT = (__nv_bfloat16*)(scr + oLSXT);
    __nv_bfloat16* lcxT = (__nv_bfloat16*)(scr + oLCXT);
    __nv_bfloat16* dsx  = (__nv_bfloat16*)(scr + oDSX);
    __nv_bfloat16* dcx  = (__nv_bfloat16*)(scr + oDCX);
    __nv_bfloat16* Wb   = (__nv_bfloat16*)(scr + oWB);
    __nv_bfloat16* Gdb  = (__nv_bfloat16*)(scr + oGDB);
    __nv_bfloat16* SlTb = (__nv_bfloat16*)(scr + oSLT);
    __nv_bfloat16* zb   = (__nv_bfloat16*)(scr + oZB);
    float* nsd = (float*)(scr + oNSD);
    float* ncd = (float*)(scr + oNCD);
    float* nsl = (float*)(scr + oNSL);
    float* ncl = (float*)(scr + oNCL);
    float* csd = (float*)(scr + oCSD);
    float* csl = (float*)(scr + oCSL);

    __nv_bfloat16* WTall = (__nv_bfloat16*)(scr + oT0);
    __nv_bfloat16* PTall = WTall + 4 * DxDc;
    __nv_bfloat16* Wc    = PTall + 4 * DxDc;
    float* ubuf = (float*)(scr + oT1);
    float* bc   = ubuf + DDIM;

    const int smemB = (2 * 128 + 2 * 256) * 72 * 2;   // 110592 B
    cudaFuncSetAttribute(hgemm<0>, cudaFuncAttributeMaxDynamicSharedMemorySize, smemB);
    cudaFuncSetAttribute(hgemm<1>, cudaFuncAttributeMaxDynamicSharedMemorySize, smemB);
    cudaFuncSetAttribute(hgemm<2>, cudaFuncAttributeMaxDynamicSharedMemorySize, smemB);
    cudaFuncSetAttribute(hgemm<3>, cudaFuncAttributeMaxDynamicSharedMemorySize, smemB);
    cudaFuncSetAttribute(hgemm<4>, cudaFuncAttributeMaxDynamicSharedMemorySize, smemB);

    const long long LxL = (long long)LDIM * LDIM;

    for (int m = 0; m < 4; ++m)
        f2b_kernel<<<2048, 256>>>(Wf[m], Wb + (long long)m * 3 * DxDc, 3LL * DxDc);
    tr_f2b<<<dim3(LDIM / 32, DDIM / 32, BBATCH), dim3(32, 8)>>>(x, xT, DDIM, LDIM);

    // --- Batched weight collapse ---
    tr_b2b<<<dim3(DDIM / 32, DDIM / 32, 4), dim3(32, 8)>>>(Wb, WTall, DDIM, DDIM,
                                                           3 * DxDc, DxDc);
    hgemm<3><<<dim3(DDIM / 256, DDIM / 128, 4), 256, smemB>>>(
        WTall, Wb + DxDc, PTall, nullptr, nullptr,
        DDIM, DDIM, DDIM, DxDc, 3 * DxDc, DxDc);
    hgemm<3><<<dim3(DDIM / 256, DDIM / 128, 4), 256, smemB>>>(
        Wb + 2 * DxDc, PTall, Wc, nullptr, nullptr,
        DDIM, DDIM, DDIM, 3 * DxDc, DxDc, DxDc);
    for (int m = 0; m < 4; ++m) {
        matvec_f<<<DDIM, 256>>>(Wf[m] + DxDc, bfv[m], bfv[m] + DDIM, ubuf, DDIM);
        matvec_f<<<DDIM, 256>>>(Wf[m] + 2 * DxDc, ubuf, bfv[m] + 2 * DDIM, bc + m * DDIM, DDIM);
    }

    // --- Single GEMM per chain ---
    __nv_bfloat16* outsT[4] = {dsxT, dcxT, lsxT, lcxT};
    for (int m = 0; m < 4; ++m) {
        dim3 g(DDIM / 256, LDIM / 128, BBATCH);
        hgemm<1><<<g, 256, smemB>>>(xT, Wc + (long long)m * DxDc, outsT[m], bc + m * DDIM,
                                    nullptr, LDIM, DDIM, DDIM, EDL, 0LL, EDL);
    }

    tr_b2b<<<dim3(DDIM / 32, LDIM / 32, BBATCH), dim3(32, 8)>>>(dsxT, dsx, LDIM, DDIM, EDL, EDL);
    tr_b2b<<<dim3(DDIM / 32, LDIM / 32, BBATCH), dim3(32, 8)>>>(dcxT, dcx, LDIM, DDIM, EDL, EDL);

    rownorm_b<<<BBATCH * DDIM, 256>>>(dsx, nsd, LDIM);
    rownorm_b<<<BBATCH * DDIM, 256>>>(dcx, ncd, LDIM);
    rownorm_b<<<BBATCH * LDIM, 256>>>(lsxT, nsl, DDIM);
    rownorm_b<<<BBATCH * LDIM, 256>>>(lcxT, ncl, DDIM);

    // Gd = cauchy(dsx · dcx^T) — fused epilogue
    hgemm<4><<<dim3(DDIM / 256, DDIM / 128, BBATCH), 256, smemB>>>(
        dsx, dcx, Gd, nsd, ncd, DDIM, DDIM, LDIM, EDL, EDL, DxDc);
    colsum<<<dim3(DDIM / 256, BBATCH), 256>>>(Gd, csd, DDIM);
    divcol_b<<<4096, 256>>>(Gd, csd, Gdb, DDIM, 20);

    // GlT = cauchy(lcxT · lsxT^T) — fused epilogue
    hgemm<4><<<dim3(LDIM / 256, LDIM / 128, BBATCH), 256, smemB>>>(
        lcxT, lsxT, GlT, ncl, nsl, LDIM, LDIM, DDIM, EDL, EDL, LxL);
    colsum<<<dim3(LDIM / 256, BBATCH), 256>>>(GlT, csl, LDIM);
    divcol_b<<<8192, 256>>>(GlT, csl, SlTb, LDIM, 22);

    // z = dscore @ x
    hgemm<3><<<dim3(LDIM / 256, DDIM / 128, BBATCH), 256, smemB>>>(
        Gdb, xT, zb, nullptr, nullptr, DDIM, LDIM, DDIM, DxDc, EDL, EDL);

    // y = (z @ lscore + x) / 2
    hgemm<2><<<dim3(LDIM / 256, DDIM / 128, BBATCH), 256, smemB>>>(
        zb, SlTb, y, nullptr, x, DDIM, LDIM, LDIM, EDL, LxL, EDL);
}

// round 16
// speedup vs baseline: 1.3015x; 1.3015x over previous
#include <cuda_runtime.h>
#include <cuda_bf16.h>
#include <cstdint>

#define BBATCH 8
#define DDIM 1024
#define LDIM 2048
#define CAUCHY_E 1.0100501670841680f
#define PI_F 3.14159265358979323846f

constexpr long long C_BDL = (long long)BBATCH * DDIM * LDIM;
constexpr long long C_BDD = (long long)BBATCH * DDIM * DDIM;
constexpr long long C_BLL = (long long)BBATCH * LDIM * LDIM;
constexpr long long C_W   = 4LL * 3 * DDIM * DDIM;
constexpr long long EDL   = (long long)DDIM * LDIM;
constexpr long long DxDc  = (long long)DDIM * DDIM;

constexpr long long oGd   = 0;
constexpr long long oGlT  = oGd   + C_BDD * 4;     // (fp32 grams now unused; kept for layout)
constexpr long long oXT   = oGlT  + C_BLL * 4;
constexpr long long oT0   = oXT   + C_BDL * 2;     // WTall, PTall, WcAll
constexpr long long oT1   = oT0   + C_BDL * 2;     // u[4][D], bc[4][D]
constexpr long long oMLP  = oT1   + C_BDL * 2;     // merged MLP out: B * L * 4096 bf16 (128MB)
constexpr long long oDSX  = oMLP  + 4 * C_BDL * 2;
constexpr long long oDCX  = oDSX  + C_BDL * 2;
constexpr long long oWB   = oDCX  + C_BDL * 2;
constexpr long long oGDB  = oWB   + C_W   * 2;
constexpr long long oSLT  = oGDB  + C_BDD * 2;
constexpr long long oZB   = oSLT  + C_BLL * 2;
constexpr long long oNSD  = oZB   + C_BDL * 2;
constexpr long long oNCD  = oNSD  + BBATCH * DDIM * 4;
constexpr long long oNSL  = oNCD  + BBATCH * DDIM * 4;
constexpr long long oNCL  = oNSL  + BBATCH * LDIM * 4;
constexpr long long oCSD  = oNCL  + BBATCH * LDIM * 4;
constexpr long long oCSL  = oCSD  + BBATCH * DDIM * 4;
constexpr long long SCRB  = oCSL  + BBATCH * LDIM * 4;
__device__ __align__(1024) unsigned char g_scr[SCRB];

// ---------------------------------------------------------------------------
__device__ __forceinline__ void ldm4(uint32_t* r, const void* p) {
    uint32_t a = (uint32_t)__cvta_generic_to_shared(p);
    asm volatile("ldmatrix.sync.aligned.m8n8.x4.shared.b16 {%0,%1,%2,%3}, [%4];"
                 : "=r"(r[0]), "=r"(r[1]), "=r"(r[2]), "=r"(r[3]) : "r"(a));
}
__device__ __forceinline__ void mma_bf16(float* d, const uint32_t* a, const uint32_t* b) {
    asm volatile(
        "mma.sync.aligned.m16n8k16.row.col.f32.bf16.bf16.f32 "
        "{%0,%1,%2,%3}, {%4,%5,%6,%7}, {%8,%9}, {%0,%1,%2,%3};"
        : "+f"(d[0]), "+f"(d[1]), "+f"(d[2]), "+f"(d[3])
        : "r"(a[0]), "r"(a[1]), "r"(a[2]), "r"(a[3]), "r"(b[0]), "r"(b[1]));
}
__device__ __forceinline__ void cpa16(void* dst, const void* src) {
    uint32_t d = (uint32_t)__cvta_generic_to_shared(dst);
    asm volatile("cp.async.cg.shared.global [%0], [%1], 16;" :: "r"(d), "l"(src));
}
__device__ __forceinline__ void cpa_commit() { asm volatile("cp.async.commit_group;"); }
template<int N>
__device__ __forceinline__ void cpa_wait() { asm volatile("cp.async.wait_group %0;" :: "n"(N)); }

// ---------------------------------------------------------------------------
// HMMA bf16 GEMM: C[M,N] = A[M,K] * B[N,K]^T, K-major bf16, row strides ldA/ldB.
// EPI: 1 +bias[col] bf16 out; 2 (acc+resid)/2 fp32 out; 3 bf16 out;
//      4 cauchy → bf16 out + atomic column sums into csum[bz*N+col]
//        (bias = row norms @ stride M/batch, resid = col norms @ stride N/batch).
// Tile 128x128x64, 8 warps (2x4, warp tile 64x32), cp.async double buffer, occ 2.
// ---------------------------------------------------------------------------
template<int EPI>
__global__ void __launch_bounds__(256, 2)
hgemm(const __nv_bfloat16* __restrict__ Ag, const __nv_bfloat16* __restrict__ Bg,
      void* __restrict__ Cg, const float* __restrict__ bias,
      const float* __restrict__ resid, float* __restrict__ csum,
      int M, int N, int K, int ldA, int ldB,
      long long sA, long long sB, long long sC)
{
    constexpr int BK = 64, LDS = 72;
    extern __shared__ __nv_bfloat16 smem[];
    __nv_bfloat16* Abase = smem;
    __nv_bfloat16* Bbase = smem + 2 * 128 * LDS;

    const int tid = threadIdx.x, lane = tid & 31, wid = tid >> 5;
    const int wR = wid & 1, wC = wid >> 1;
    const int bz = blockIdx.z;
    const __nv_bfloat16* A = Ag + bz * sA;
    const __nv_bfloat16* B = Bg + bz * sB;
    const int mBase = blockIdx.y * 128, nBase = blockIdx.x * 128;
    const int mW = wR * 64, nW = wC * 32;

    auto fetch = [&](int t, int buf) {
        const int kb = t * BK;
#pragma unroll
        for (int i = 0; i < 4; ++i) {
            const int fi = tid + i * 256;
            const int r = fi >> 3, c = (fi & 7) << 3;
            cpa16(Abase + (buf * 128 + r) * LDS + c,
                  A + (long long)(mBase + r) * ldA + kb + c);
        }
#pragma unroll
        for (int i = 0; i < 4; ++i) {
            const int fi = tid + i * 256;
            const int r = fi >> 3, c = (fi & 7) << 3;
            cpa16(Bbase + (buf * 128 + r) * LDS + c,
                  B + (long long)(nBase + r) * ldB + kb + c);
        }
        cpa_commit();
    };

    float acc[4][4][4] = {};
    const int nT = K / BK;

    fetch(0, 0);
    for (int t = 0; t < nT; ++t) {
        const int buf = t & 1;
        if (t + 1 < nT) { fetch(t + 1, buf ^ 1); cpa_wait<1>(); }
        else            { cpa_wait<0>(); }
        __syncthreads();

        const __nv_bfloat16* As = Abase + buf * 128 * LDS;
        const __nv_bfloat16* Bs = Bbase + buf * 128 * LDS;
#pragma unroll
        for (int kk = 0; kk < BK; kk += 16) {
            uint32_t a[4][4], b[4][2];
#pragma unroll
            for (int mt = 0; mt < 4; ++mt)
                ldm4(a[mt], As + (mW + mt * 16 + (lane & 15)) * LDS + kk + ((lane >> 4) << 3));
#pragma unroll
            for (int p = 0; p < 2; ++p) {
                uint32_t r4[4];
                ldm4(r4, Bs + (nW + p * 16 + (lane & 15)) * LDS + kk + ((lane >> 4) << 3));
                b[2 * p + 0][0] = r4[0]; b[2 * p + 0][1] = r4[2];
                b[2 * p + 1][0] = r4[1]; b[2 * p + 1][1] = r4[3];
            }
#pragma unroll
            for (int mt = 0; mt < 4; ++mt)
#pragma unroll
                for (int nt = 0; nt < 4; ++nt)
                    mma_bf16(acc[mt][nt], a[mt], b[nt]);
        }
        __syncthreads();
    }

    const int g = lane >> 2, tq = lane & 3;
    float part[4][2] = {};
#pragma unroll
    for (int mt = 0; mt < 4; ++mt) {
#pragma unroll
        for (int half = 0; half < 2; ++half) {
            const int row = mBase + mW + mt * 16 + g + half * 8;
            const float nsr = (EPI == 4) ? __ldg(&bias[(long long)bz * M + row]) : 0.f;
#pragma unroll
            for (int nt = 0; nt < 4; ++nt) {
                const int col = nBase + nW + nt * 8 + tq * 2;
                const long long off = (long long)row * N + col;
                float v0 = acc[mt][nt][half * 2 + 0];
                float v1 = acc[mt][nt][half * 2 + 1];
                if (EPI == 1) {
                    v0 += __ldg(&bias[col]);
                    v1 += __ldg(&bias[col + 1]);
                }
                if (EPI == 2) {
                    float* C = (float*)Cg + bz * sC + off;
                    const float* Rp = resid + bz * sC + off;
                    float2 r2 = *reinterpret_cast<const float2*>(Rp);
                    *reinterpret_cast<float2*>(C) = make_float2((v0 + r2.x) * 0.5f,
                                                                (v1 + r2.y) * 0.5f);
                } else if (EPI == 4) {
                    const float nc0 = __ldg(&resid[(long long)bz * N + col]);
                    const float nc1 = __ldg(&resid[(long long)bz * N + col + 1]);
                    float w0 = __powf((v0 * v0) / (nsr * nc0), CAUCHY_E);
                    float w1 = __powf((v1 * v1) / (nsr * nc1), CAUCHY_E);
                    if (row == col) w0 -= 1.f;
                    if (row == col + 1) w1 -= 1.f;
                    w0 = fmaxf(0.5f - 0.5f * __cosf(PI_F * w0), 0.f);
                    w1 = fmaxf(0.5f - 0.5f * __cosf(PI_F * w1), 0.f);
                    float e0 = __expf(w0), e1 = __expf(w1);
                    __nv_bfloat162 h = __floats2bfloat162_rn(e0, e1);
                    // store the bf16-rounded values and sum exactly those
                    e0 = __bfloat162float(__low2bfloat16(h));
                    e1 = __bfloat162float(__high2bfloat16(h));
                    part[nt][0] += e0; part[nt][1] += e1;
                    __nv_bfloat16* C = (__nv_bfloat16*)Cg + bz * sC + off;
                    *reinterpret_cast<__nv_bfloat162*>(C) = h;
                } else {
                    __nv_bfloat16* C = (__nv_bfloat16*)Cg + bz * sC + off;
                    *reinterpret_cast<__nv_bfloat162*>(C) = __floats2bfloat162_rn(v0, v1);
                }
            }
        }
    }
    if (EPI == 4) {
#pragma unroll
        for (int nt = 0; nt < 4; ++nt) {
#pragma unroll
            for (int j = 0; j < 2; ++j) {
                float s = part[nt][j];
                s += __shfl_xor_sync(0xFFFFFFFFu, s, 4);
                s += __shfl_xor_sync(0xFFFFFFFFu, s, 8);
                s += __shfl_xor_sync(0xFFFFFFFFu, s, 16);
                if (g == 0)
                    atomicAdd(&csum[(long long)bz * N + nBase + nW + nt * 8 + tq * 2 + j], s);
            }
        }
    }
}

// ----------------------------- elementwise --------------------------------
__device__ __forceinline__ float block_reduce_sum(float v) {
    __shared__ float sh[32];
#pragma unroll
    for (int o = 16; o; o >>= 1) v += __shfl_xor_sync(0xFFFFFFFFu, v, o);
    const int lane = threadIdx.x & 31, w = threadIdx.x >> 5;
    if (lane == 0) sh[w] = v;
    __syncthreads();
    if (w == 0) {
        v = (lane < (int)(blockDim.x >> 5)) ? sh[lane] : 0.f;
#pragma unroll
        for (int o = 16; o; o >>= 1) v += __shfl_xor_sync(0xFFFFFFFFu, v, o);
        if (lane == 0) sh[0] = v;
    }
    __syncthreads();
    return sh[0];
}

// convert 4 weight stacks in one launch (blockIdx.y selects tensor)
__global__ void f2b4_kernel(const float* __restrict__ w0, const float* __restrict__ w1,
                            const float* __restrict__ w2, const float* __restrict__ w3,
                            __nv_bfloat16* __restrict__ out, long long n) {
    const float* src[4] = {w0, w1, w2, w3};
    const float* in = src[blockIdx.y];
    __nv_bfloat16* o = out + (long long)blockIdx.y * n;
    for (long long i = (long long)blockIdx.x * blockDim.x + threadIdx.x; i < n;
         i += (long long)gridDim.x * blockDim.x)
        o[i] = __float2bfloat16(in[i]);
}

__global__ void tr_f2b(const float* __restrict__ in, __nv_bfloat16* __restrict__ out, int R, int C) {
    __shared__ float sh[32][33];
    const long long bb = blockIdx.z;
    const float* I = in + bb * (long long)R * C;
    __nv_bfloat16* O = out + bb * (long long)R * C;
    const int c0 = blockIdx.x * 32, r0 = blockIdx.y * 32;
    const int tx = threadIdx.x, ty = threadIdx.y;
#pragma unroll
    for (int i = 0; i < 32; i += 8) sh[ty + i][tx] = I[(long long)(r0 + ty + i) * C + c0 + tx];
    __syncthreads();
#pragma unroll
    for (int i = 0; i < 32; i += 8)
        O[(long long)(c0 + ty + i) * R + r0 + tx] = __float2bfloat16(sh[tx][ty + i]);
}

// transpose [R,C] (row stride ldIn) -> [C,R] contiguous; batched via strides
__global__ void tr_b2b(const __nv_bfloat16* __restrict__ in, __nv_bfloat16* __restrict__ out,
                       int R, int C, int ldIn, long long inStride, long long outStride) {
    __shared__ __nv_bfloat16 sh[32][33];
    const long long bb = blockIdx.z;
    const __nv_bfloat16* I = in + bb * inStride;
    __nv_bfloat16* O = out + bb * outStride;
    const int c0 = blockIdx.x * 32, r0 = blockIdx.y * 32;
    const int tx = threadIdx.x, ty = threadIdx.y;
#pragma unroll
    for (int i = 0; i < 32; i += 8) sh[ty + i][tx] = I[(long long)(r0 + ty + i) * ldIn + c0 + tx];
    __syncthreads();
#pragma unroll
    for (int i = 0; i < 32; i += 8) O[(long long)(c0 + ty + i) * R + r0 + tx] = sh[tx][ty + i];
}

// batched mat-vec over 4 chains: out[m][row] = sum_i W_m[row,i]*v_m[i] + b_m[row]
__global__ void matvec4(const float* __restrict__ Wa, const float* __restrict__ Wb2,
                        const float* __restrict__ Wc2, const float* __restrict__ Wd,
                        const float* __restrict__ va, const float* __restrict__ vb,
                        const float* __restrict__ vc, const float* __restrict__ vd,
                        const float* __restrict__ ba, const float* __restrict__ bb,
                        const float* __restrict__ bc2, const float* __restrict__ bd,
                        float* __restrict__ out, int n) {
    const float* Ws[4] = {Wa, Wb2, Wc2, Wd};
    const float* vs[4] = {va, vb, vc, vd};
    const float* bs[4] = {ba, bb, bc2, bd};
    const int m = blockIdx.y, row = blockIdx.x;
    const float* w = Ws[m] + (long long)row * n;
    const float* v = vs[m];
    float s = 0.f;
    for (int i = threadIdx.x; i < n; i += blockDim.x) s = fmaf(w[i], v[i], s);
    s = block_reduce_sum(s);
    if (threadIdx.x == 0) out[(long long)m * n + row] = s + bs[m][row];
}

// row sums of squares; row r of batch b at X + b*bStride + r*ld, length C
__global__ void rownorm_b(const __nv_bfloat16* __restrict__ X, float* __restrict__ out,
                          int C, int ld, int rowsPerBatch, long long bStride) {
    const int bi = blockIdx.x;
    const int b = bi / rowsPerBatch, r = bi % rowsPerBatch;
    const __nv_bfloat16* p = X + b * bStride + (long long)r * ld;
    float s = 0.f;
    for (int i = threadIdx.x; i < C; i += blockDim.x) {
        float v = __bfloat162float(p[i]);
        s = fmaf(v, v, s);
    }
    s = block_reduce_sum(s);
    if (threadIdx.x == 0) out[bi] = s;
}

__global__ void zero_f(float* __restrict__ p, long long n) {
    for (long long i = (long long)blockIdx.x * blockDim.x + threadIdx.x; i < n;
         i += (long long)gridDim.x * blockDim.x) p[i] = 0.f;
}

// in-place: G[idx] = bf16(float(G[idx]) / cs[b*n + col])
__global__ void divcol_ip(__nv_bfloat16* __restrict__ G, const float* __restrict__ cs,
                          int n, int sq_shift) {
    const long long tot = (long long)BBATCH * n * n;
    for (long long idx = (long long)blockIdx.x * blockDim.x + threadIdx.x; idx < tot;
         idx += (long long)gridDim.x * blockDim.x) {
        const int q = (int)(idx & (n - 1));
        const int b = (int)(idx >> sq_shift);
        G[idx] = __float2bfloat16(__bfloat162float(G[idx]) / cs[b * n + q]);
    }
}

// ---------------------------------------------------------------------------
extern "C" void kernel_launch(void* const* d_in, const int* in_sizes, int n_in,
                              void* d_out, int out_size) {
    const float* x = (const float*)d_in[0];
    const float* Wf[4] = {(const float*)d_in[1], (const float*)d_in[3],
                          (const float*)d_in[5], (const float*)d_in[7]};
    const float* bfv[4] = {(const float*)d_in[2], (const float*)d_in[4],
                           (const float*)d_in[6], (const float*)d_in[8]};
    float* y = (float*)d_out;

    unsigned char* scr = nullptr;
    cudaGetSymbolAddress((void**)&scr, g_scr);

    __nv_bfloat16* xT   = (__nv_bfloat16*)(scr + oXT);
    __nv_bfloat16* Wb   = (__nv_bfloat16*)(scr + oWB);
    __nv_bfloat16* mlp  = (__nv_bfloat16*)(scr + oMLP);   // [B][L][4096]
    __nv_bfloat16* dsx  = (__nv_bfloat16*)(scr + oDSX);
    __nv_bfloat16* dcx  = (__nv_bfloat16*)(scr + oDCX);
    __nv_bfloat16* Gdb  = (__nv_bfloat16*)(scr + oGDB);
    __nv_bfloat16* SlTb = (__nv_bfloat16*)(scr + oSLT);
    __nv_bfloat16* zb   = (__nv_bfloat16*)(scr + oZB);
    float* nsd = (float*)(scr + oNSD);
    float* ncd = (float*)(scr + oNCD);
    float* nsl = (float*)(scr + oNSL);
    float* ncl = (float*)(scr + oNCL);
    float* csd = (float*)(scr + oCSD);
    float* csl = (float*)(scr + oCSL);

    __nv_bfloat16* WTall = (__nv_bfloat16*)(scr + oT0);
    __nv_bfloat16* PTall = WTall + 4 * DxDc;
    __nv_bfloat16* WcAll = PTall + 4 * DxDc;              // [4][D][D] = merged B operand
    float* ubuf = (float*)(scr + oT1);                    // [4][D]
    float* bc   = ubuf + 4 * DDIM;                        // [4][D] = merged bias (4096)

    const int smemB = 4 * 128 * 72 * 2;   // 73728 B
    cudaFuncSetAttribute(hgemm<1>, cudaFuncAttributeMaxDynamicSharedMemorySize, smemB);
    cudaFuncSetAttribute(hgemm<2>, cudaFuncAttributeMaxDynamicSharedMemorySize, smemB);
    cudaFuncSetAttribute(hgemm<3>, cudaFuncAttributeMaxDynamicSharedMemorySize, smemB);
    cudaFuncSetAttribute(hgemm<4>, cudaFuncAttributeMaxDynamicSharedMemorySize, smemB);

    const long long LxL = (long long)LDIM * LDIM;
    const long long M4  = 4 * EDL;                        // per-batch stride of merged MLP out

    // weights -> bf16 (one launch), x -> xT
    f2b4_kernel<<<dim3(512, 4), 256>>>(Wf[0], Wf[1], Wf[2], Wf[3], Wb, 3LL * DxDc);
    tr_f2b<<<dim3(LDIM / 32, DDIM / 32, BBATCH), dim3(32, 8)>>>(x, xT, DDIM, LDIM);

    // --- batched weight collapse: WcAll_m = W2_m W1_m W0_m ---
    tr_b2b<<<dim3(DDIM / 32, DDIM / 32, 4), dim3(32, 8)>>>(Wb, WTall, DDIM, DDIM, DDIM,
                                                           3 * DxDc, DxDc);
    hgemm<3><<<dim3(8, 8, 4), 256, smemB>>>(WTall, Wb + DxDc, PTall, nullptr, nullptr, nullptr,
                                            DDIM, DDIM, DDIM, DDIM, DDIM, DxDc, 3 * DxDc, DxDc);
    hgemm<3><<<dim3(8, 8, 4), 256, smemB>>>(Wb + 2 * DxDc, PTall, WcAll, nullptr, nullptr, nullptr,
                                            DDIM, DDIM, DDIM, DDIM, DDIM, 3 * DxDc, DxDc, DxDc);
    // bias chains, batched over the 4 chains (2 launches)
    matvec4<<<dim3(DDIM, 4), 256>>>(Wf[0] + DxDc, Wf[1] + DxDc, Wf[2] + DxDc, Wf[3] + DxDc,
                                    bfv[0], bfv[1], bfv[2], bfv[3],
                                    bfv[0] + DDIM, bfv[1] + DDIM, bfv[2] + DDIM, bfv[3] + DDIM,
                                    ubuf, DDIM);
    matvec4<<<dim3(DDIM, 4), 256>>>(Wf[0] + 2 * DxDc, Wf[1] + 2 * DxDc, Wf[2] + 2 * DxDc, Wf[3] + 2 * DxDc,
                                    ubuf, ubuf + DDIM, ubuf + 2 * DDIM, ubuf + 3 * DDIM,
                                    bfv[0] + 2 * DDIM, bfv[1] + 2 * DDIM, bfv[2] + 2 * DDIM, bfv[3] + 2 * DDIM,
                                    bc, DDIM);

    // --- merged MLP: mlp[b][l][m*1024+o] = sum_i xT[b][l][i] WcAll[m][o][i] + bc[m][o] ---
    hgemm<1><<<dim3(4096 / 128, LDIM / 128, BBATCH), 256, smemB>>>(
        xT, WcAll, mlp, bc, nullptr, nullptr,
        LDIM, 4096, DDIM, DDIM, DDIM, EDL, 0LL, M4);

    __nv_bfloat16* dsxT = mlp;                  // chain slices (row stride 4096)
    __nv_bfloat16* dcxT = mlp + 1024;
    __nv_bfloat16* lsxT = mlp + 2 * 1024;
    __nv_bfloat16* lcxT = mlp + 3 * 1024;

    // d-path operands back to [D,L]
    tr_b2b<<<dim3(DDIM / 32, LDIM / 32, BBATCH), dim3(32, 8)>>>(dsxT, dsx, LDIM, DDIM, 4096, M4, EDL);
    tr_b2b<<<dim3(DDIM / 32, LDIM / 32, BBATCH), dim3(32, 8)>>>(dcxT, dcx, LDIM, DDIM, 4096, M4, EDL);

    // norms
    rownorm_b<<<BBATCH * DDIM, 256>>>(dsx, nsd, LDIM, LDIM, DDIM, EDL);
    rownorm_b<<<BBATCH * DDIM, 256>>>(dcx, ncd, LDIM, LDIM, DDIM, EDL);
    rownorm_b<<<BBATCH * LDIM, 256>>>(lsxT, nsl, DDIM, 4096, LDIM, M4);
    rownorm_b<<<BBATCH * LDIM, 256>>>(lcxT, ncl, DDIM, 4096, LDIM, M4);

    // zero softmax denominators (csd and csl are adjacent)
    zero_f<<<32, 256>>>(csd, BBATCH * (DDIM + LDIM));

    // Gd (bf16) = cauchy(dsx · dcx^T) with fused column sums
    hgemm<4><<<dim3(DDIM / 128, DDIM / 128, BBATCH), 256, smemB>>>(
        dsx, dcx, Gdb, nsd, ncd, csd,
        DDIM, DDIM, LDIM, LDIM, LDIM, EDL, EDL, DxDc);
    divcol_ip<<<4096, 256>>>(Gdb, csd, DDIM, 20);

    // GlT (bf16) = cauchy(lcxT · lsxT^T) with fused column sums
    hgemm<4><<<dim3(LDIM / 128, LDIM / 128, BBATCH), 256, smemB>>>(
        lcxT, lsxT, SlTb, ncl, nsl, csl,
        LDIM, LDIM, DDIM, 4096, 4096, M4, M4, LxL);
    divcol_ip<<<8192, 256>>>(SlTb, csl, LDIM, 22);

    // z = dscore @ x
    hgemm<3><<<dim3(LDIM / 128, DDIM / 128, BBATCH), 256, smemB>>>(
        Gdb, xT, zb, nullptr, nullptr, nullptr,
        DDIM, LDIM, DDIM, DDIM, DDIM, DxDc, EDL, EDL);

    // y = (z @ lscore + x) / 2
    hgemm<2><<<dim3(LDIM / 128, DDIM / 128, BBATCH), 256, smemB>>>(
        zb, SlTb, y, nullptr, x, nullptr,
        DDIM, LDIM, LDIM, LDIM, LDIM, EDL, LxL, EDL);
}

// round 17
// speedup vs baseline: 1.3485x; 1.0361x over previous
#include <cuda_runtime.h>
#include <cuda_bf16.h>
#include <cstdint>

#define BBATCH 8
#define DDIM 1024
#define LDIM 2048
#define CAUCHY_E 1.0100501670841680f
#define PI_F 3.14159265358979323846f

constexpr long long C_BDL = (long long)BBATCH * DDIM * LDIM;
constexpr long long C_BDD = (long long)BBATCH * DDIM * DDIM;
constexpr long long C_BLL = (long long)BBATCH * LDIM * LDIM;
constexpr long long C_W   = 4LL * 3 * DDIM * DDIM;
constexpr long long EDL   = (long long)DDIM * LDIM;
constexpr long long DxDc  = (long long)DDIM * DDIM;

constexpr long long oPAD  = 0;
constexpr long long oXT   = oPAD  + C_BDD * 4 + C_BLL * 4;   // keep prior footprint shape
constexpr long long oT0   = oXT   + C_BDL * 2;               // WTall, PTall, WcAll
constexpr long long oT1   = oT0   + C_BDL * 2;               // u[4][D], bc[4][D]
constexpr long long oMLP  = oT1   + C_BDL * 2;               // dsxdcx (2*C_BDL) + mlpL (2*C_BDL)
constexpr long long oWB   = oMLP  + 4 * C_BDL * 2;
constexpr long long oGDB  = oWB   + C_W   * 2;
constexpr long long oSLT  = oGDB  + C_BDD * 2;
constexpr long long oZB   = oSLT  + C_BLL * 2;
constexpr long long oNSD  = oZB   + C_BDL * 2;
constexpr long long oNCD  = oNSD  + BBATCH * DDIM * 4;
constexpr long long oNSL  = oNCD  + BBATCH * DDIM * 4;
constexpr long long oNCL  = oNSL  + BBATCH * LDIM * 4;
constexpr long long oCSD  = oNCL  + BBATCH * LDIM * 4;
constexpr long long oCSL  = oCSD  + BBATCH * DDIM * 4;
constexpr long long SCRB  = oCSL  + BBATCH * LDIM * 4;
__device__ __align__(1024) unsigned char g_scr[SCRB];

// ---------------------------------------------------------------------------
__device__ __forceinline__ void ldm4(uint32_t* r, const void* p) {
    uint32_t a = (uint32_t)__cvta_generic_to_shared(p);
    asm volatile("ldmatrix.sync.aligned.m8n8.x4.shared.b16 {%0,%1,%2,%3}, [%4];"
                 : "=r"(r[0]), "=r"(r[1]), "=r"(r[2]), "=r"(r[3]) : "r"(a));
}
__device__ __forceinline__ void mma_bf16(float* d, const uint32_t* a, const uint32_t* b) {
    asm volatile(
        "mma.sync.aligned.m16n8k16.row.col.f32.bf16.bf16.f32 "
        "{%0,%1,%2,%3}, {%4,%5,%6,%7}, {%8,%9}, {%0,%1,%2,%3};"
        : "+f"(d[0]), "+f"(d[1]), "+f"(d[2]), "+f"(d[3])
        : "r"(a[0]), "r"(a[1]), "r"(a[2]), "r"(a[3]), "r"(b[0]), "r"(b[1]));
}
__device__ __forceinline__ void cpa16(void* dst, const void* src) {
    uint32_t d = (uint32_t)__cvta_generic_to_shared(dst);
    asm volatile("cp.async.cg.shared.global [%0], [%1], 16;" :: "r"(d), "l"(src));
}
__device__ __forceinline__ void cpa_commit() { asm volatile("cp.async.commit_group;"); }
template<int N>
__device__ __forceinline__ void cpa_wait() { asm volatile("cp.async.wait_group %0;" :: "n"(N)); }

// ---------------------------------------------------------------------------
// HMMA bf16 GEMM: C[M,N] = A[M,K] * B[N,K]^T, K-major bf16, row strides ldA/ldB.
// EPI: 1 +bias[col] bf16; 2 (acc+resid)/2 fp32; 3 bf16;
//      4 cauchy → bf16 + atomic col sums into csum[bz*N+col]
//        (bias = row norms stride M/batch, resid = col norms stride N/batch);
//      5 +bias[row] bf16; 6 *rcp(csum[bz*N+col]) bf16.
// Tile 128x128x64, 8 warps (2x4), cp.async double buffer, occ 2.
// ---------------------------------------------------------------------------
template<int EPI>
__global__ void __launch_bounds__(256, 2)
hgemm(const __nv_bfloat16* __restrict__ Ag, const __nv_bfloat16* __restrict__ Bg,
      void* __restrict__ Cg, const float* __restrict__ bias,
      const float* __restrict__ resid, float* __restrict__ csum,
      int M, int N, int K, int ldA, int ldB,
      long long sA, long long sB, long long sC)
{
    constexpr int BK = 64, LDS = 72;
    extern __shared__ __nv_bfloat16 smem[];
    __nv_bfloat16* Abase = smem;
    __nv_bfloat16* Bbase = smem + 2 * 128 * LDS;

    const int tid = threadIdx.x, lane = tid & 31, wid = tid >> 5;
    const int wR = wid & 1, wC = wid >> 1;
    const int bz = blockIdx.z;
    const __nv_bfloat16* A = Ag + bz * sA;
    const __nv_bfloat16* B = Bg + bz * sB;
    const int mBase = blockIdx.y * 128, nBase = blockIdx.x * 128;
    const int mW = wR * 64, nW = wC * 32;

    auto fetch = [&](int t, int buf) {
        const int kb = t * BK;
#pragma unroll
        for (int i = 0; i < 4; ++i) {
            const int fi = tid + i * 256;
            const int r = fi >> 3, c = (fi & 7) << 3;
            cpa16(Abase + (buf * 128 + r) * LDS + c,
                  A + (long long)(mBase + r) * ldA + kb + c);
        }
#pragma unroll
        for (int i = 0; i < 4; ++i) {
            const int fi = tid + i * 256;
            const int r = fi >> 3, c = (fi & 7) << 3;
            cpa16(Bbase + (buf * 128 + r) * LDS + c,
                  B + (long long)(nBase + r) * ldB + kb + c);
        }
        cpa_commit();
    };

    float acc[4][4][4] = {};
    const int nT = K / BK;

    fetch(0, 0);
    for (int t = 0; t < nT; ++t) {
        const int buf = t & 1;
        if (t + 1 < nT) { fetch(t + 1, buf ^ 1); cpa_wait<1>(); }
        else            { cpa_wait<0>(); }
        __syncthreads();

        const __nv_bfloat16* As = Abase + buf * 128 * LDS;
        const __nv_bfloat16* Bs = Bbase + buf * 128 * LDS;
#pragma unroll
        for (int kk = 0; kk < BK; kk += 16) {
            uint32_t a[4][4], b[4][2];
#pragma unroll
            for (int mt = 0; mt < 4; ++mt)
                ldm4(a[mt], As + (mW + mt * 16 + (lane & 15)) * LDS + kk + ((lane >> 4) << 3));
#pragma unroll
            for (int p = 0; p < 2; ++p) {
                uint32_t r4[4];
                ldm4(r4, Bs + (nW + p * 16 + (lane & 15)) * LDS + kk + ((lane >> 4) << 3));
                b[2 * p + 0][0] = r4[0]; b[2 * p + 0][1] = r4[2];
                b[2 * p + 1][0] = r4[1]; b[2 * p + 1][1] = r4[3];
            }
#pragma unroll
            for (int mt = 0; mt < 4; ++mt)
#pragma unroll
                for (int nt = 0; nt < 4; ++nt)
                    mma_bf16(acc[mt][nt], a[mt], b[nt]);
        }
        __syncthreads();
    }

    const int g = lane >> 2, tq = lane & 3;
    float part[4][2] = {};
#pragma unroll
    for (int mt = 0; mt < 4; ++mt) {
#pragma unroll
        for (int half = 0; half < 2; ++half) {
            const int row = mBase + mW + mt * 16 + g + half * 8;
            const float rowf = (EPI == 4) ? __ldg(&bias[(long long)bz * M + row])
                             : (EPI == 5) ? __ldg(&bias[row]) : 0.f;
#pragma unroll
            for (int nt = 0; nt < 4; ++nt) {
                const int col = nBase + nW + nt * 8 + tq * 2;
                const long long off = (long long)row * N + col;
                float v0 = acc[mt][nt][half * 2 + 0];
                float v1 = acc[mt][nt][half * 2 + 1];
                if (EPI == 1) {
                    v0 += __ldg(&bias[col]);
                    v1 += __ldg(&bias[col + 1]);
                } else if (EPI == 5) {
                    v0 += rowf; v1 += rowf;
                } else if (EPI == 6) {
                    v0 /= __ldg(&csum[(long long)bz * N + col]);
                    v1 /= __ldg(&csum[(long long)bz * N + col + 1]);
                }
                if (EPI == 2) {
                    float* C = (float*)Cg + bz * sC + off;
                    const float* Rp = resid + bz * sC + off;
                    float2 r2 = *reinterpret_cast<const float2*>(Rp);
                    *reinterpret_cast<float2*>(C) = make_float2((v0 + r2.x) * 0.5f,
                                                                (v1 + r2.y) * 0.5f);
                } else if (EPI == 4) {
                    const float nc0 = __ldg(&resid[(long long)bz * N + col]);
                    const float nc1 = __ldg(&resid[(long long)bz * N + col + 1]);
                    float w0 = __powf((v0 * v0) / (rowf * nc0), CAUCHY_E);
                    float w1 = __powf((v1 * v1) / (rowf * nc1), CAUCHY_E);
                    if (row == col) w0 -= 1.f;
                    if (row == col + 1) w1 -= 1.f;
                    w0 = fmaxf(0.5f - 0.5f * __cosf(PI_F * w0), 0.f);
                    w1 = fmaxf(0.5f - 0.5f * __cosf(PI_F * w1), 0.f);
                    float e0 = __expf(w0), e1 = __expf(w1);
                    __nv_bfloat162 h = __floats2bfloat162_rn(e0, e1);
                    part[nt][0] += __bfloat162float(__low2bfloat16(h));
                    part[nt][1] += __bfloat162float(__high2bfloat16(h));
                    __nv_bfloat16* C = (__nv_bfloat16*)Cg + bz * sC + off;
                    *reinterpret_cast<__nv_bfloat162*>(C) = h;
                } else {
                    __nv_bfloat16* C = (__nv_bfloat16*)Cg + bz * sC + off;
                    *reinterpret_cast<__nv_bfloat162*>(C) = __floats2bfloat162_rn(v0, v1);
                }
            }
        }
    }
    if (EPI == 4) {
#pragma unroll
        for (int nt = 0; nt < 4; ++nt) {
#pragma unroll
            for (int j = 0; j < 2; ++j) {
                float s = part[nt][j];
                s += __shfl_xor_sync(0xFFFFFFFFu, s, 4);
                s += __shfl_xor_sync(0xFFFFFFFFu, s, 8);
                s += __shfl_xor_sync(0xFFFFFFFFu, s, 16);
                if (g == 0)
                    atomicAdd(&csum[(long long)bz * N + nBase + nW + nt * 8 + tq * 2 + j], s);
            }
        }
    }
}

// ----------------------------- elementwise --------------------------------
__device__ __forceinline__ float block_reduce_sum(float v) {
    __shared__ float sh[32];
#pragma unroll
    for (int o = 16; o; o >>= 1) v += __shfl_xor_sync(0xFFFFFFFFu, v, o);
    const int lane = threadIdx.x & 31, w = threadIdx.x >> 5;
    if (lane == 0) sh[w] = v;
    __syncthreads();
    if (w == 0) {
        v = (lane < (int)(blockDim.x >> 5)) ? sh[lane] : 0.f;
#pragma unroll
        for (int o = 16; o; o >>= 1) v += __shfl_xor_sync(0xFFFFFFFFu, v, o);
        if (lane == 0) sh[0] = v;
    }
    __syncthreads();
    return sh[0];
}

__global__ void f2b4_kernel(const float* __restrict__ w0, const float* __restrict__ w1,
                            const float* __restrict__ w2, const float* __restrict__ w3,
                            __nv_bfloat16* __restrict__ out, long long n) {
    const float* src[4] = {w0, w1, w2, w3};
    const float* in = src[blockIdx.y];
    __nv_bfloat16* o = out + (long long)blockIdx.y * n;
    for (long long i = (long long)blockIdx.x * blockDim.x + threadIdx.x; i < n;
         i += (long long)gridDim.x * blockDim.x)
        o[i] = __float2bfloat16(in[i]);
}

__global__ void tr_f2b(const float* __restrict__ in, __nv_bfloat16* __restrict__ out, int R, int C) {
    __shared__ float sh[32][33];
    const long long bb = blockIdx.z;
    const float* I = in + bb * (long long)R * C;
    __nv_bfloat16* O = out + bb * (long long)R * C;
    const int c0 = blockIdx.x * 32, r0 = blockIdx.y * 32;
    const int tx = threadIdx.x, ty = threadIdx.y;
#pragma unroll
    for (int i = 0; i < 32; i += 8) sh[ty + i][tx] = I[(long long)(r0 + ty + i) * C + c0 + tx];
    __syncthreads();
#pragma unroll
    for (int i = 0; i < 32; i += 8)
        O[(long long)(c0 + ty + i) * R + r0 + tx] = __float2bfloat16(sh[tx][ty + i]);
}

__global__ void tr_b2b(const __nv_bfloat16* __restrict__ in, __nv_bfloat16* __restrict__ out,
                       int R, int C, int ldIn, long long inStride, long long outStride) {
    __shared__ __nv_bfloat16 sh[32][33];
    const long long bb = blockIdx.z;
    const __nv_bfloat16* I = in + bb * inStride;
    __nv_bfloat16* O = out + bb * outStride;
    const int c0 = blockIdx.x * 32, r0 = blockIdx.y * 32;
    const int tx = threadIdx.x, ty = threadIdx.y;
#pragma unroll
    for (int i = 0; i < 32; i += 8) sh[ty + i][tx] = I[(long long)(r0 + ty + i) * ldIn + c0 + tx];
    __syncthreads();
#pragma unroll
    for (int i = 0; i < 32; i += 8) O[(long long)(c0 + ty + i) * R + r0 + tx] = sh[tx][ty + i];
}

__global__ void matvec4(const float* __restrict__ Wa, const float* __restrict__ Wb2,
                        const float* __restrict__ Wc2, const float* __restrict__ Wd,
                        const float* __restrict__ va, const float* __restrict__ vb,
                        const float* __restrict__ vc, const float* __restrict__ vd,
                        const float* __restrict__ ba, const float* __restrict__ bb,
                        const float* __restrict__ bc2, const float* __restrict__ bd,
                        float* __restrict__ out, int n) {
    const float* Ws[4] = {Wa, Wb2, Wc2, Wd};
    const float* vs[4] = {va, vb, vc, vd};
    const float* bs[4] = {ba, bb, bc2, bd};
    const int m = blockIdx.y, row = blockIdx.x;
    const float* w = Ws[m] + (long long)row * n;
    const float* v = vs[m];
    float s = 0.f;
    for (int i = threadIdx.x; i < n; i += blockDim.x) s = fmaf(w[i], v[i], s);
    s = block_reduce_sum(s);
    if (threadIdx.x == 0) out[(long long)m * n + row] = s + bs[m][row];
}

__global__ void rownorm_b(const __nv_bfloat16* __restrict__ X, float* __restrict__ out,
                          int C, int ld, int rowsPerBatch, long long bStride) {
    const int bi = blockIdx.x;
    const int b = bi / rowsPerBatch, r = bi % rowsPerBatch;
    const __nv_bfloat16* p = X + b * bStride + (long long)r * ld;
    float s = 0.f;
    for (int i = threadIdx.x; i < C; i += blockDim.x) {
        float v = __bfloat162float(p[i]);
        s = fmaf(v, v, s);
    }
    s = block_reduce_sum(s);
    if (threadIdx.x == 0) out[bi] = s;
}

__global__ void zero_f(float* __restrict__ p, long long n) {
    for (long long i = (long long)blockIdx.x * blockDim.x + threadIdx.x; i < n;
         i += (long long)gridDim.x * blockDim.x) p[i] = 0.f;
}

__global__ void divcol_ip(__nv_bfloat16* __restrict__ G, const float* __restrict__ cs,
                          int n, int sq_shift) {
    const long long tot = (long long)BBATCH * n * n;
    for (long long idx = (long long)blockIdx.x * blockDim.x + threadIdx.x; idx < tot;
         idx += (long long)gridDim.x * blockDim.x) {
        const int q = (int)(idx & (n - 1));
        const int b = (int)(idx >> sq_shift);
        G[idx] = __float2bfloat16(__bfloat162float(G[idx]) / cs[b * n + q]);
    }
}

// ---------------------------------------------------------------------------
extern "C" void kernel_launch(void* const* d_in, const int* in_sizes, int n_in,
                              void* d_out, int out_size) {
    const float* x = (const float*)d_in[0];
    const float* Wf[4] = {(const float*)d_in[1], (const float*)d_in[3],
                          (const float*)d_in[5], (const float*)d_in[7]};
    const float* bfv[4] = {(const float*)d_in[2], (const float*)d_in[4],
                           (const float*)d_in[6], (const float*)d_in[8]};
    float* y = (float*)d_out;

    unsigned char* scr = nullptr;
    cudaGetSymbolAddress((void**)&scr, g_scr);

    __nv_bfloat16* xT   = (__nv_bfloat16*)(scr + oXT);
    __nv_bfloat16* Wb   = (__nv_bfloat16*)(scr + oWB);
    __nv_bfloat16* dsxdcx = (__nv_bfloat16*)(scr + oMLP);            // [B][2048][L]
    __nv_bfloat16* mlpL   = dsxdcx + 2 * C_BDL;                      // [B][L][2048]
    __nv_bfloat16* Gdb  = (__nv_bfloat16*)(scr + oGDB);
    __nv_bfloat16* SlTb = (__nv_bfloat16*)(scr + oSLT);
    __nv_bfloat16* zb   = (__nv_bfloat16*)(scr + oZB);
    float* nsd = (float*)(scr + oNSD);
    float* ncd = (float*)(scr + oNCD);
    float* nsl = (float*)(scr + oNSL);
    float* ncl = (float*)(scr + oNCL);
    float* csd = (float*)(scr + oCSD);
    float* csl = (float*)(scr + oCSL);

    __nv_bfloat16* WTall = (__nv_bfloat16*)(scr + oT0);
    __nv_bfloat16* PTall = WTall + 4 * DxDc;
    __nv_bfloat16* WcAll = PTall + 4 * DxDc;              // [4][D][D]
    float* ubuf = (float*)(scr + oT1);                    // [4][D]
    float* bc   = ubuf + 4 * DDIM;                        // [4][D]

    const int smemB = 4 * 128 * 72 * 2;
    cudaFuncSetAttribute(hgemm<1>, cudaFuncAttributeMaxDynamicSharedMemorySize, smemB);
    cudaFuncSetAttribute(hgemm<2>, cudaFuncAttributeMaxDynamicSharedMemorySize, smemB);
    cudaFuncSetAttribute(hgemm<3>, cudaFuncAttributeMaxDynamicSharedMemorySize, smemB);
    cudaFuncSetAttribute(hgemm<4>, cudaFuncAttributeMaxDynamicSharedMemorySize, smemB);
    cudaFuncSetAttribute(hgemm<5>, cudaFuncAttributeMaxDynamicSharedMemorySize, smemB);
    cudaFuncSetAttribute(hgemm<6>, cudaFuncAttributeMaxDynamicSharedMemorySize, smemB);

    const long long LxL = (long long)LDIM * LDIM;
    const long long S2  = 2 * EDL;

    f2b4_kernel<<<dim3(512, 4), 256>>>(Wf[0], Wf[1], Wf[2], Wf[3], Wb, 3LL * DxDc);
    tr_f2b<<<dim3(LDIM / 32, DDIM / 32, BBATCH), dim3(32, 8)>>>(x, xT, DDIM, LDIM);

    // --- batched weight collapse ---
    tr_b2b<<<dim3(DDIM / 32, DDIM / 32, 4), dim3(32, 8)>>>(Wb, WTall, DDIM, DDIM, DDIM,
                                                           3 * DxDc, DxDc);
    hgemm<3><<<dim3(8, 8, 4), 256, smemB>>>(WTall, Wb + DxDc, PTall, nullptr, nullptr, nullptr,
                                            DDIM, DDIM, DDIM, DDIM, DDIM, DxDc, 3 * DxDc, DxDc);
    hgemm<3><<<dim3(8, 8, 4), 256, smemB>>>(Wb + 2 * DxDc, PTall, WcAll, nullptr, nullptr, nullptr,
                                            DDIM, DDIM, DDIM, DDIM, DDIM, 3 * DxDc, DxDc, DxDc);
    matvec4<<<dim3(DDIM, 4), 256>>>(Wf[0] + DxDc, Wf[1] + DxDc, Wf[2] + DxDc, Wf[3] + DxDc,
                                    bfv[0], bfv[1], bfv[2], bfv[3],
                                    bfv[0] + DDIM, bfv[1] + DDIM, bfv[2] + DDIM, bfv[3] + DDIM,
                                    ubuf, DDIM);
    matvec4<<<dim3(DDIM, 4), 256>>>(Wf[0] + 2 * DxDc, Wf[1] + 2 * DxDc, Wf[2] + 2 * DxDc, Wf[3] + 2 * DxDc,
                                    ubuf, ubuf + DDIM, ubuf + 2 * DDIM, ubuf + 3 * DDIM,
                                    bfv[0] + 2 * DDIM, bfv[1] + 2 * DDIM, bfv[2] + 2 * DDIM, bfv[3] + 2 * DDIM,
                                    bc, DDIM);

    // --- d-chain MLPs, output-transposed: dsxdcx[b][o(0..2047)][l] ---
    // rows 0..1023 = dsx, 1024..2047 = dcx; row bias bc[0..2048)
    hgemm<5><<<dim3(LDIM / 128, 2048 / 128, BBATCH), 256, smemB>>>(
        WcAll, xT, dsxdcx, bc, nullptr, nullptr,
        2048, LDIM, DDIM, DDIM, DDIM, 0LL, EDL, S2);

    // --- l-chain MLPs: mlpL[b][l][o(0..2047)]; col bias bc[2048..4096) ---
    hgemm<1><<<dim3(2048 / 128, LDIM / 128, BBATCH), 256, smemB>>>(
        xT, WcAll + 2 * DxDc, mlpL, bc + 2048, nullptr, nullptr,
        LDIM, 2048, DDIM, DDIM, DDIM, EDL, 0LL, S2);

    __nv_bfloat16* dsx  = dsxdcx;              // [D,L], batch stride S2
    __nv_bfloat16* dcx  = dsxdcx + EDL;
    __nv_bfloat16* lsxT = mlpL;                // [L,2048-ld], batch stride S2
    __nv_bfloat16* lcxT = mlpL + 1024;

    // norms
    rownorm_b<<<BBATCH * DDIM, 256>>>(dsx, nsd, LDIM, LDIM, DDIM, S2);
    rownorm_b<<<BBATCH * DDIM, 256>>>(dcx, ncd, LDIM, LDIM, DDIM, S2);
    rownorm_b<<<BBATCH * LDIM, 256>>>(lsxT, nsl, DDIM, 2048, LDIM, S2);
    rownorm_b<<<BBATCH * LDIM, 256>>>(lcxT, ncl, DDIM, 2048, LDIM, S2);

    zero_f<<<32, 256>>>(csd, BBATCH * (DDIM + LDIM));

    // Gd (bf16) = cauchy(dsx · dcx^T) + fused column sums
    hgemm<4><<<dim3(DDIM / 128, DDIM / 128, BBATCH), 256, smemB>>>(
        dsx, dcx, Gdb, nsd, ncd, csd,
        DDIM, DDIM, LDIM, LDIM, LDIM, S2, S2, DxDc);
    divcol_ip<<<4096, 256>>>(Gdb, csd, DDIM, 20);

    // GlT raw (bf16) = cauchy(lcxT · lsxT^T) + fused column sums (no divide)
    hgemm<4><<<dim3(LDIM / 128, LDIM / 128, BBATCH), 256, smemB>>>(
        lcxT, lsxT, SlTb, ncl, nsl, csl,
        LDIM, LDIM, DDIM, 2048, 2048, S2, S2, LxL);

    // z = dscore @ x, columns scaled by 1/csl (folds lscore normalization)
    hgemm<6><<<dim3(LDIM / 128, DDIM / 128, BBATCH), 256, smemB>>>(
        Gdb, xT, zb, nullptr, nullptr, csl,
        DDIM, LDIM, DDIM, DDIM, DDIM, DxDc, EDL, EDL);

    // y = (z @ GlT_raw^T + x) / 2
    hgemm<2><<<dim3(LDIM / 128, DDIM / 128, BBATCH), 256, smemB>>>(
        zb, SlTb, y, nullptr, x, nullptr,
        DDIM, LDIM, LDIM, LDIM, LDIM, EDL, LxL, EDL);
}